// round 2
// baseline (speedup 1.0000x reference)
#include <cuda_runtime.h>

#define BDIM 8
#define FDIM 64
#define NROWS (BDIM * BDIM * FDIM)   // 4096

// scratch: per-row contribution (already scaled by label and 1/F)
__device__ float g_row[NROWS];

__global__ __launch_bounds__(FDIM) void row_kernel(
    const float* __restrict__ sim,
    const float* __restrict__ pos,
    const float* __restrict__ neg,
    const float* __restrict__ label)
{
    __shared__ float sP[FDIM];    // sims where p[k]==1
    __shared__ float sN0[FDIM];   // sims where p[k]==0 && n[k]==1
    __shared__ int   cP[2], cN[2];
    __shared__ float warpsum[2];

    const int row  = blockIdx.x;
    const int tid  = threadIdx.x;
    const int base = row * FDIM;

    const float v    = sim[base + tid];
    const bool  isP  = (pos[base + tid] != 0.0f);
    const bool  isN0 = (!isP) && (neg[base + tid] != 0.0f);

    const int warp = tid >> 5;
    const int lane = tid & 31;
    const unsigned mP = __ballot_sync(0xffffffffu, isP);
    const unsigned mN = __ballot_sync(0xffffffffu, isN0);
    if (lane == 0) { cP[warp] = __popc(mP); cN[warp] = __popc(mN); }
    __syncthreads();

    const unsigned lt = (1u << lane) - 1u;
    const int offP = (warp ? cP[0] : 0) + __popc(mP & lt);
    const int offN = (warp ? cN[0] : 0) + __popc(mN & lt);
    if (isP)  sP[offP]  = v;
    if (isN0) sN0[offN] = v;
    const int nP  = cP[0] + cP[1];
    const int nN0 = cN[0] + cN[1];
    __syncthreads();

    float ratio = 0.0f;
    if (isP) {
        const float sj = v;
        // pos_rk - 1 = 10 * #{k in P : s[k] > s[j]}  (strict > excludes k==j)
        int cnt = 0;
        #pragma unroll 4
        for (int m = 0; m < nP; m++)
            cnt += (sP[m] > sj) ? 1 : 0;

        // quad_linear sum over N0 (disjoint from P -> no diagonal exclusion)
        float qs = 0.0f;
        #pragma unroll 4
        for (int m = 0; m < nN0; m++) {
            float t = (sN0[m] - sj) * 10.0f;   // x / sigma
            float u = t + 1.0f;
            float w = fmaxf(u, 0.0f);
            // x>0 : 2t+1 = u+t ; -1<=t<=0 : (t+1)^2 ; t<-1 : 0
            qs += (t > 0.0f) ? (u + t) : (w * w);
        }

        float prk = 1.0f + 10.0f * (float)cnt;
        ratio = prk / (prk + qs);
    }

    // deterministic block reduction of ratio over 64 threads
    #pragma unroll
    for (int s = 16; s > 0; s >>= 1)
        ratio += __shfl_down_sync(0xffffffffu, ratio, s);
    if (lane == 0) warpsum[warp] = ratio;
    __syncthreads();

    if (tid == 0) {
        float tot = warpsum[0] + warpsum[1];
        float lab = label[row >> 6];                      // row / FDIM -> (b1*B+b2)
        float rv  = (nP > 0) ? (tot / (float)nP) : 0.0f;  // pos_divide / pos_cnt
        g_row[row] = rv * lab * (1.0f / (float)FDIM);     // mean over i + label mask
    }
}

__global__ __launch_bounds__(256) void final_kernel(
    const float* __restrict__ label, float* __restrict__ out)
{
    __shared__ float sh[256];
    const int tid = threadIdx.x;
    float s = 0.0f;
    for (int i = tid; i < NROWS; i += 256) s += g_row[i];   // fixed order -> deterministic
    sh[tid] = s;
    __syncthreads();
    #pragma unroll
    for (int st = 128; st > 0; st >>= 1) {
        if (tid < st) sh[tid] += sh[tid + st];
        __syncthreads();
    }
    if (tid == 0) {
        float den = 0.0f;
        #pragma unroll
        for (int i = 0; i < BDIM * BDIM; i++) den += label[i];
        out[0] = 1.0f - sh[0] / den;
    }
}

extern "C" void kernel_launch(void* const* d_in, const int* in_sizes, int n_in,
                              void* d_out, int out_size)
{
    const float* sim   = (const float*)d_in[0];
    const float* pos   = (const float*)d_in[1];
    const float* neg   = (const float*)d_in[2];
    const float* label = (const float*)d_in[3];
    float* out = (float*)d_out;

    row_kernel<<<NROWS, FDIM>>>(sim, pos, neg, label);
    final_kernel<<<1, 256>>>(label, out);
}

// round 7
// speedup vs baseline: 1.1805x; 1.1805x over previous
#include <cuda_runtime.h>

#define BDIM 8
#define FDIM 64
#define NROWS (BDIM * BDIM * FDIM)     // 4096
#define ROWS_PER_BLK 8
#define NBLK (NROWS / ROWS_PER_BLK)    // 512
#define BLKT (ROWS_PER_BLK * FDIM)     // 512 threads

// persistent accumulators; zero at load, and every completed call resets them
__device__ unsigned long long g_acc = 0ULL;   // Q48 fixed-point sum of ap terms
__device__ unsigned int       g_cnt = 0u;     // blocks-done counter

#define Q48 281474976710656.0           // 2^48

__global__ __launch_bounds__(BLKT) void ap_kernel(
    const float* __restrict__ sim,
    const float* __restrict__ pos,
    const float* __restrict__ neg,
    const float* __restrict__ label,
    float* __restrict__ out)
{
    __shared__ float sP [ROWS_PER_BLK][FDIM];
    __shared__ float sN0[ROWS_PER_BLK][FDIM];
    __shared__ int   cP [ROWS_PER_BLK][2], cN[ROWS_PER_BLK][2];
    __shared__ float wsum[ROWS_PER_BLK * 2];
    __shared__ float rowval[ROWS_PER_BLK];

    const int tid  = threadIdx.x;
    const int r    = tid >> 6;          // row within block (0..7)
    const int half = (tid >> 5) & 1;    // which 32-lane half of the row
    const int lane = tid & 31;
    const int row  = blockIdx.x * ROWS_PER_BLK + r;   // global row
    const int base = row * FDIM + (tid & 63);

    const float v    = sim[base];
    const bool  isP  = (pos[base] != 0.0f);
    const bool  isN0 = (!isP) && (neg[base] != 0.0f);

    const unsigned mP = __ballot_sync(0xffffffffu, isP);
    const unsigned mN = __ballot_sync(0xffffffffu, isN0);
    if (lane == 0) { cP[r][half] = __popc(mP); cN[r][half] = __popc(mN); }
    __syncthreads();

    const unsigned lt = (1u << lane) - 1u;
    const int offP = (half ? cP[r][0] : 0) + __popc(mP & lt);
    const int offN = (half ? cN[r][0] : 0) + __popc(mN & lt);
    if (isP)  sP [r][offP] = v;
    if (isN0) sN0[r][offN] = v;
    const int nP  = cP[r][0] + cP[r][1];
    const int nN0 = cN[r][0] + cN[r][1];
    __syncthreads();

    float ratio = 0.0f;
    if (isP) {
        const float sj = v;
        int cnt = 0;
        #pragma unroll 4
        for (int m = 0; m < nP; m++)
            cnt += (sP[r][m] > sj) ? 1 : 0;

        float qs = 0.0f;
        #pragma unroll 4
        for (int m = 0; m < nN0; m++) {
            float t = (sN0[r][m] - sj) * 10.0f;   // x / sigma
            float u = t + 1.0f;
            float w = fmaxf(u, 0.0f);
            qs += (t > 0.0f) ? (u + t) : (w * w); // 2t+1 | (t+1)^2 | 0
        }
        float prk = 1.0f + 10.0f * (float)cnt;
        ratio = prk / (prk + qs);
    }

    // per-warp reduction (each warp = half a row)
    #pragma unroll
    for (int s = 16; s > 0; s >>= 1)
        ratio += __shfl_down_sync(0xffffffffu, ratio, s);
    if (lane == 0) wsum[(tid >> 5)] = ratio;
    __syncthreads();

    if ((tid & 63) == 0) {
        float tot = wsum[2 * r] + wsum[2 * r + 1];
        rowval[r] = (nP > 0) ? (tot / (float)nP) : 0.0f;   // pos_divide / pos_cnt
    }
    __syncthreads();

    if (tid == 0) {
        // all 8 rows of this block belong to the same (b1,b2) pair
        const float lab = label[blockIdx.x >> 3];
        float bs = 0.0f;
        #pragma unroll
        for (int i = 0; i < ROWS_PER_BLK; i++) bs += rowval[i];
        bs *= lab * (1.0f / (float)FDIM);                  // mean over i + label mask

        unsigned long long q = (unsigned long long)llrint((double)bs * Q48);
        atomicAdd(&g_acc, q);
        __threadfence();
        unsigned done = atomicAdd(&g_cnt, 1u);
        if (done == (unsigned)(gridDim.x - 1)) {
            unsigned long long acc = atomicAdd(&g_acc, 0ULL);  // coherent read
            float den = 0.0f;
            #pragma unroll
            for (int i = 0; i < BDIM * BDIM; i++) den += label[i];
            out[0] = 1.0f - (float)((double)acc * (1.0 / Q48)) / den;
            // reset for next call / graph replay (deterministic, single thread)
            atomicExch(&g_acc, 0ULL);
            atomicExch(&g_cnt, 0u);
        }
    }
}

extern "C" void kernel_launch(void* const* d_in, const int* in_sizes, int n_in,
                              void* d_out, int out_size)
{
    const float* sim   = (const float*)d_in[0];
    const float* pos   = (const float*)d_in[1];
    const float* neg   = (const float*)d_in[2];
    const float* label = (const float*)d_in[3];
    float* out = (float*)d_out;

    ap_kernel<<<NBLK, BLKT>>>(sim, pos, neg, label, out);
}